// round 16
// baseline (speedup 1.0000x reference)
#include <cuda_runtime.h>
#include <cuda_fp16.h>

#define NX    512
#define NPTS  32768
#define CCH   64
#define NB    4
#define PLANE (NX * NX)
#define BVOL  (PLANE * CCH)
#define CH    32                  // channels per half

// NHWC fp16 scratch, per half: (h, b, pixel, c32). One half = 67 MB (L2-fits).
__device__ __half g_xt[(size_t)NB * BVOL];

// ---------------------------------------------------------------------------
// Kernel 1: half-transpose. Tile = 64 px x 32 ch of half h -> NHWC fp16.
// Grid NB*4096 x 256. 2x LDG.128 + 1x STG.128 per thread.
// ---------------------------------------------------------------------------
__global__ __launch_bounds__(256) void transpose_kernel(const float* __restrict__ x,
                                                        int h)
{
    __shared__ float s[CH][65];               // [channel][pixel]

    const int tile = blockIdx.x;
    const int b    = tile >> 12;              // 4096 tiles per batch
    const int p0   = (tile & 4095) * 64;

    const int slot = threadIdx.x & 15;        // float4 slot (4 px)
    const int c0   = threadIdx.x >> 4;        // 0..15

    const float* xb = x + ((size_t)b * CCH + h * CH) * PLANE;
    #pragma unroll
    for (int c = c0; c < CH; c += 16) {
        const float4 v = __ldcs((const float4*)(xb + (size_t)c * PLANE + p0 + slot * 4));
        s[c][slot * 4 + 0] = v.x;
        s[c][slot * 4 + 1] = v.y;
        s[c][slot * 4 + 2] = v.z;
        s[c][slot * 4 + 3] = v.w;
    }
    __syncthreads();

    __half* yb = g_xt + ((size_t)(h * NB + b) * PLANE + p0) * CH;
    {
        const int i   = threadIdx.x;          // 256 = 64 px x 4 octets
        const int p   = i >> 2;               // pixel
        const int oct = i & 3;                // 8-channel octet
        __half2 hx[4];
        #pragma unroll
        for (int j = 0; j < 4; j++)
            hx[j] = __floats2half2_rn(s[oct * 8 + 2 * j][p], s[oct * 8 + 2 * j + 1][p]);
        *(int4*)(yb + (size_t)p * CH + oct * 8) = *(const int4*)hx;   // STG.128
    }
}

// ---------------------------------------------------------------------------
// Kernel 2: half-gather. Block = 256 threads, 32 consecutive points x 32 ch.
// Phase 1: warp 0 computes weights (round-10 shape). Phase 2: one iteration,
// lane = (point 0..3, channel quad 0..7), LDG.64 per tap from L2-hot scratch.
// Phase 3: scalar stores, (c, n)-coalesced (round-10 shape).
// ---------------------------------------------------------------------------
__global__ __launch_bounds__(256) void gather_kernel(
    const float* __restrict__ coords,
    float*       __restrict__ out,
    int h)
{
    __shared__ __align__(16) float s_w[32][12];    // 9 used, 48B rows
    __shared__ __align__(16) int   s_off[32][12];  // half-elem offsets (x32)
    __shared__ float s_out[CH][33];                // [channel][point]

    const int p0g = blockIdx.x * 32;
    const int b   = p0g / NPTS;
    const int n0  = p0g % NPTS;
    const int tid = threadIdx.x;

    // ---- Phase 1: per-point normalized 3x3 weights + offsets (warp 0) ----
    if (tid < 32) {
        const int   n    = n0 + tid;
        const float cy   = coords[((size_t)b * NPTS + n) * 2 + 0];
        const float cx   = coords[((size_t)b * NPTS + n) * 2 + 1];
        const float posx = cx * 511.0f;
        const float posy = cy * 511.0f;
        const float rx   = rintf(posx);       // jnp.round = half-to-even
        const float ry   = rintf(posy);

        float wx[3] = {0.f, 0.f, 0.f};
        float wy[3] = {0.f, 0.f, 0.f};
        #pragma unroll
        for (int j = 0; j < 9; j++) {
            const float o  = 1.5f - 0.375f * (float)j;           // off_n[j]
            const float px = fminf(fmaxf(rx - o, 0.f), 512.f);   // clip hi = nx (ref quirk)
            const float py = fminf(fmaxf(ry - o, 0.f), 512.f);
            const float dx = px - posx;
            const float dy = py - posy;
            wx[j / 3] += __expf(-2.f * dx * dx);  // normal const cancels in norm
            wy[j / 3] += __expf(-2.f * dy * dy);
        }

        float w9[9];
        float s = 0.f;
        #pragma unroll
        for (int a = 0; a < 3; a++)
            #pragma unroll
            for (int c2 = 0; c2 < 3; c2++) {
                const float w = wx[a] * wy[c2];
                w9[a * 3 + c2] = w;
                s += w;
            }
        const float inv = 1.0f / s;

        const int irx = (int)rx;
        const int iry = (int)ry;
        int ixs[3], iys[3];
        #pragma unroll
        for (int a = 0; a < 3; a++) {
            ixs[a] = min(max(irx + 1 - a, 0), NX - 1);
            iys[a] = min(max(iry + 1 - a, 0), NX - 1);
        }

        #pragma unroll
        for (int a = 0; a < 3; a++)
            #pragma unroll
            for (int c2 = 0; c2 < 3; c2++) {
                s_w[tid][a * 3 + c2]   = w9[a * 3 + c2] * inv;
                s_off[tid][a * 3 + c2] = (ixs[a] * NX + iys[c2]) * CH;
            }
    }
    __syncthreads();

    // ---- Phase 2: dense fp16 gather from L2-hot scratch, LDG.64 per tap ----
    const int lane = tid & 31;
    const int warp = tid >> 5;
    const int cq   = lane & 7;                // channel quad (4 ch of 32)
    const int q    = lane >> 3;               // point select (0..3)
    const int p    = warp * 4 + q;            // point index in block
    const __half* bp = g_xt + (size_t)(h * NB + b) * PLANE * CH + 4 * cq;

    const int4 oA = *(const int4*)&s_off[p][0];
    const int4 oB = *(const int4*)&s_off[p][4];
    const int  o8 = s_off[p][8];
    const int off[9] = {oA.x, oA.y, oA.z, oA.w, oB.x, oB.y, oB.z, oB.w, o8};

    const float4 wA = *(const float4*)&s_w[p][0];
    const float4 wB = *(const float4*)&s_w[p][4];
    const float  w8 = s_w[p][8];
    const float w[9] = {wA.x, wA.y, wA.z, wA.w, wB.x, wB.y, wB.z, wB.w, w8};

    int2 v[9];
    #pragma unroll
    for (int k = 0; k < 9; k++)
        v[k] = *(const int2*)(bp + off[k]);       // LDG.64, 4 channels

    float ax = 0.f, ay = 0.f, az = 0.f, aw = 0.f;
    #pragma unroll
    for (int k = 0; k < 9; k++) {
        const float2 f0 = __half22float2(*(const __half2*)&v[k].x);
        const float2 f1 = __half22float2(*(const __half2*)&v[k].y);
        ax += w[k] * f0.x;  ay += w[k] * f0.y;
        az += w[k] * f1.x;  aw += w[k] * f1.y;
    }
    s_out[4 * cq + 0][p] = ax;
    s_out[4 * cq + 1][p] = ay;
    s_out[4 * cq + 2][p] = az;
    s_out[4 * cq + 3][p] = aw;
    __syncthreads();

    // ---- Phase 3: coalesced (c, n) scalar writes ----
    float* ob = out + (size_t)b * CCH * NPTS + (size_t)(h * CH) * NPTS + n0;
    #pragma unroll
    for (int i = tid; i < CH * 32; i += 256) {
        const int j = i & 31;
        const int c = i >> 5;
        __stcs(ob + (size_t)c * NPTS + j, s_out[c][j]);
    }
}

extern "C" void kernel_launch(void* const* d_in, const int* in_sizes, int n_in,
                              void* d_out, int out_size) {
    const float* x      = (const float*)d_in[0];
    const float* coords = (const float*)d_in[1];
    if (n_in >= 2 && in_sizes[0] == NB * NPTS * 2) {   // defensive swap
        const float* t = x; x = coords; coords = t;
    }
    float* out = (float*)d_out;

    // Channel-halved pipeline: each gather reads scratch (67 MB, L2-resident)
    // written by the immediately preceding transpose.
    for (int h = 0; h < 2; h++) {
        transpose_kernel<<<NB * (PLANE / 64), 256>>>(x, h);
        gather_kernel<<<(NB * NPTS) / 32, 256>>>(coords, out, h);
    }
}